// round 3
// baseline (speedup 1.0000x reference)
#include <cuda_runtime.h>
#include <cuda_bf16.h>

#define MAXN 100000
#define MAXE 1600000
#define IN_C 128
#define OUT_C 64

// ---------------------------------------------------------------------------
// Scratch (__device__ globals per allocation-free rule)
__device__ float g_xw[(size_t)MAXN * OUT_C];   // projected features [N,64]
__device__ int   g_cnt[MAXN];                  // histogram -> running fill offsets
__device__ int   g_rowptr[MAXN + 1];           // CSR row pointers (by dst)
__device__ int   g_esrc[MAXE];                 // src ids sorted by dst
__device__ float g_dinv[MAXN];                 // rsqrt(deg)

// ---------------------------------------------------------------------------
__global__ void cnt_zero_kernel(int n) {
    int i = blockIdx.x * blockDim.x + threadIdx.x;
    if (i < n) g_cnt[i] = 0;
}

__global__ void hist_kernel(const int* __restrict__ dst, int e) {
    int i = blockIdx.x * blockDim.x + threadIdx.x;
    if (i < e) atomicAdd(&g_cnt[dst[i]], 1);
}

// dinv = rsqrt(in_deg + 1)   (+1 for self-loop)
__global__ void dinv_kernel(int n) {
    int i = blockIdx.x * blockDim.x + threadIdx.x;
    if (i < n) g_dinv[i] = rsqrtf((float)(g_cnt[i] + 1));
}

// Single-block exclusive scan with carry. Writes g_rowptr[0..n] and resets
// g_cnt[i] to the row start (running offsets for the fill pass).
__global__ __launch_bounds__(1024) void scan_kernel(int n) {
    __shared__ int sh[1024];
    __shared__ int carry;
    if (threadIdx.x == 0) carry = 0;
    __syncthreads();

    for (int base = 0; base < n; base += 1024) {
        int i = base + (int)threadIdx.x;
        int v = (i < n) ? g_cnt[i] : 0;
        sh[threadIdx.x] = v;
        __syncthreads();
        #pragma unroll
        for (int off = 1; off < 1024; off <<= 1) {
            int t = (threadIdx.x >= off) ? sh[threadIdx.x - off] : 0;
            __syncthreads();
            sh[threadIdx.x] += t;
            __syncthreads();
        }
        int incl = sh[threadIdx.x];
        int excl = incl - v + carry;
        if (i < n) { g_rowptr[i] = excl; g_cnt[i] = excl; }
        __syncthreads();
        if (threadIdx.x == 1023) carry += sh[1023];
        __syncthreads();
    }
    if (threadIdx.x == 0) g_rowptr[n] = carry;
}

// Scatter edge sources into dst-sorted order.
__global__ void fill_kernel(const int* __restrict__ src,
                            const int* __restrict__ dst, int e) {
    int i = blockIdx.x * blockDim.x + threadIdx.x;
    if (i < e) {
        int d = dst[i];
        int pos = atomicAdd(&g_cnt[d], 1);
        g_esrc[pos] = src[i];
    }
}

// ---------------------------------------------------------------------------
// GEMM: xw = x @ W  (to g_xw) + fused self-loop epilogue:
//   out[r] = xw[r]*dinv[r]^2 + bias   (initializes poisoned d_out)
// 32 rows x 64 cols per 256-thread block, full K=128.
__global__ __launch_bounds__(256) void gemm_kernel(
    const float* __restrict__ x,
    const float* __restrict__ w,      // [128,64] row-major
    const float* __restrict__ bias,   // [64]
    float* __restrict__ out,          // [N,64]
    int n)
{
    __shared__ float  xs[32 * 128];   // 16 KB
    __shared__ float4 ws[128 * 16];   // 32 KB

    const int tid = threadIdx.x;
    const int r0  = blockIdx.x * 32;

    const float4* w4 = (const float4*)w;
    #pragma unroll
    for (int i = tid; i < 2048; i += 256) ws[i] = w4[i];

    const float4* x4  = (const float4*)x;
    float4*       xs4 = (float4*)xs;
    #pragma unroll
    for (int i = tid; i < 1024; i += 256) {
        int row = i >> 5, c4 = i & 31;
        int r = r0 + row;
        xs4[i] = (r < n) ? x4[(size_t)r * 32 + c4] : make_float4(0.f, 0.f, 0.f, 0.f);
    }
    __syncthreads();

    const int tx = tid & 15;   // 4 cols (float4)
    const int ty = tid >> 4;   // 2 rows

    float4 acc0 = make_float4(0.f, 0.f, 0.f, 0.f);
    float4 acc1 = make_float4(0.f, 0.f, 0.f, 0.f);
    const float* xrow0 = &xs[(ty * 2 + 0) * 128];
    const float* xrow1 = &xs[(ty * 2 + 1) * 128];

    #pragma unroll 8
    for (int k = 0; k < 128; k++) {
        float4 wv = ws[k * 16 + tx];
        float a0 = xrow0[k];
        float a1 = xrow1[k];
        acc0.x += a0 * wv.x; acc0.y += a0 * wv.y; acc0.z += a0 * wv.z; acc0.w += a0 * wv.w;
        acc1.x += a1 * wv.x; acc1.y += a1 * wv.y; acc1.z += a1 * wv.z; acc1.w += a1 * wv.w;
    }

    float4 bv   = ((const float4*)bias)[tx];
    float4* xw4 = (float4*)g_xw;
    float4* out4 = (float4*)out;

    #pragma unroll
    for (int i = 0; i < 2; i++) {
        int r = r0 + ty * 2 + i;
        if (r < n) {
            float4 a = i ? acc1 : acc0;
            xw4[(size_t)r * 16 + tx] = a;
            float di = g_dinv[r];
            float dd = di * di;
            float4 o;
            o.x = a.x * dd + bv.x;
            o.y = a.y * dd + bv.y;
            o.z = a.z * dd + bv.z;
            o.w = a.w * dd + bv.w;
            out4[(size_t)r * 16 + tx] = o;
        }
    }
}

// ---------------------------------------------------------------------------
// Gather-reduce: one warp per node. Lane owns cols [2*lane, 2*lane+1].
// Exclusive node ownership -> no float atomics.
__global__ __launch_bounds__(256) void gather_kernel(
    float* __restrict__ out, int n)
{
    int wid  = (blockIdx.x * blockDim.x + threadIdx.x) >> 5;
    int lane = threadIdx.x & 31;
    if (wid >= n) return;

    int start = g_rowptr[wid];
    int end   = g_rowptr[wid + 1];
    float di  = g_dinv[wid];

    float2 acc = make_float2(0.f, 0.f);

    #pragma unroll 4
    for (int k = start; k < end; k++) {
        int s = __ldg(&g_esrc[k]);                 // broadcast across warp
        float nrm = di * __ldg(&g_dinv[s]);
        float2 v = *(const float2*)(g_xw + (size_t)s * 64 + lane * 2);
        acc.x += v.x * nrm;
        acc.y += v.y * nrm;
    }

    float2* o = (float2*)(out + (size_t)wid * 64);
    float2 cur = o[lane];
    cur.x += acc.x;
    cur.y += acc.y;
    o[lane] = cur;
}

// ---------------------------------------------------------------------------
extern "C" void kernel_launch(void* const* d_in, const int* in_sizes, int n_in,
                              void* d_out, int out_size) {
    const float* x    = (const float*)d_in[0];
    const int*   ei   = (const int*)d_in[1];     // [2, E] int32 (JAX x64 off)
    const float* w    = (const float*)d_in[2];   // [128, 64]
    const float* bias = (const float*)d_in[3];   // [64]
    float*       out  = (float*)d_out;

    const int n = in_sizes[0] / IN_C;
    const int e = in_sizes[1] / 2;

    const int* src = ei;        // edge_index[0] (message sources)
    const int* dst = ei + e;    // edge_index[1] (aggregation targets)

    // CSR build (by dst) + normalization
    cnt_zero_kernel<<<(n + 255) / 256, 256>>>(n);
    hist_kernel<<<(e + 255) / 256, 256>>>(dst, e);
    dinv_kernel<<<(n + 255) / 256, 256>>>(n);
    scan_kernel<<<1, 1024>>>(n);
    fill_kernel<<<(e + 255) / 256, 256>>>(src, dst, e);

    // xw = x @ W, self-loop + bias epilogue initializes out
    gemm_kernel<<<(n + 31) / 32, 256>>>(x, w, bias, out, n);

    // atomic-free scatter: warp-per-node gather-reduce
    int blocks = (n * 32 + 255) / 256;
    gather_kernel<<<blocks, 256>>>(out, n);
}

// round 4
// speedup vs baseline: 1.8034x; 1.8034x over previous
#include <cuda_runtime.h>
#include <cuda_bf16.h>

#define MAXN 100000
#define MAXE 1600000
#define IN_C 128
#define OUT_C 64
#define SCAN_BLK 1024
#define MAX_SCAN_BLOCKS 128   // ceil(100000/1024) = 98

// ---------------------------------------------------------------------------
// Scratch (__device__ globals per allocation-free rule)
__device__ float g_xw[(size_t)MAXN * OUT_C];   // projected features [N,64]
__device__ int   g_cnt[MAXN];                  // histogram -> running fill offsets
__device__ int   g_rowptr[MAXN + 1];           // CSR row pointers (by dst)
__device__ int   g_esrc[MAXE];                 // src ids sorted by dst
__device__ float g_dinv[MAXN];                 // rsqrt(deg)
__device__ int   g_blocksum[MAX_SCAN_BLOCKS];  // per-block totals
__device__ int   g_blockoff[MAX_SCAN_BLOCKS];  // exclusive-scanned totals

// ---------------------------------------------------------------------------
__global__ void cnt_zero_kernel(int n) {
    int i = blockIdx.x * blockDim.x + threadIdx.x;
    if (i < n) g_cnt[i] = 0;
}

__global__ void hist_kernel(const int* __restrict__ dst, int e) {
    int i = blockIdx.x * blockDim.x + threadIdx.x;
    if (i < e) atomicAdd(&g_cnt[dst[i]], 1);
}

// dinv = rsqrt(in_deg + 1)   (+1 for self-loop)
__global__ void dinv_kernel(int n) {
    int i = blockIdx.x * blockDim.x + threadIdx.x;
    if (i < n) g_dinv[i] = rsqrtf((float)(g_cnt[i] + 1));
}

// ---------------------------------------------------------------------------
// Parallel scan, pass A: per-block exclusive scan of g_cnt, block totals out.
__global__ __launch_bounds__(SCAN_BLK) void scanA_kernel(int n) {
    __shared__ int sh[SCAN_BLK];
    int i = blockIdx.x * SCAN_BLK + threadIdx.x;
    int v = (i < n) ? g_cnt[i] : 0;
    sh[threadIdx.x] = v;
    __syncthreads();
    #pragma unroll
    for (int off = 1; off < SCAN_BLK; off <<= 1) {
        int t = (threadIdx.x >= off) ? sh[threadIdx.x - off] : 0;
        __syncthreads();
        sh[threadIdx.x] += t;
        __syncthreads();
    }
    if (i < n) g_rowptr[i] = sh[threadIdx.x] - v;   // exclusive, block-local
    if (threadIdx.x == SCAN_BLK - 1) g_blocksum[blockIdx.x] = sh[SCAN_BLK - 1];
}

// Pass B: exclusive scan of block sums (single warp-sized problem, 1 block).
__global__ __launch_bounds__(128) void scanB_kernel(int nblocks) {
    __shared__ int sh[128];
    int v = (threadIdx.x < nblocks) ? g_blocksum[threadIdx.x] : 0;
    sh[threadIdx.x] = v;
    __syncthreads();
    #pragma unroll
    for (int off = 1; off < 128; off <<= 1) {
        int t = (threadIdx.x >= off) ? sh[threadIdx.x - off] : 0;
        __syncthreads();
        sh[threadIdx.x] += t;
        __syncthreads();
    }
    if (threadIdx.x < nblocks) g_blockoff[threadIdx.x] = sh[threadIdx.x] - v;
}

// Pass C: add block offsets; init g_cnt to row starts; set rowptr[n]=e.
__global__ void scanC_kernel(int n, int e) {
    int i = blockIdx.x * blockDim.x + threadIdx.x;
    if (i < n) {
        int r = g_rowptr[i] + g_blockoff[i / SCAN_BLK];
        g_rowptr[i] = r;
        g_cnt[i]    = r;
    }
    if (i == 0) g_rowptr[n] = e;
}

// Scatter edge sources into dst-sorted order.
__global__ void fill_kernel(const int* __restrict__ src,
                            const int* __restrict__ dst, int e) {
    int i = blockIdx.x * blockDim.x + threadIdx.x;
    if (i < e) {
        int d = dst[i];
        int pos = atomicAdd(&g_cnt[d], 1);
        g_esrc[pos] = src[i];
    }
}

// ---------------------------------------------------------------------------
// GEMM: xw = x @ W  (to g_xw) + fused self-loop epilogue:
//   out[r] = xw[r]*dinv[r]^2 + bias   (initializes poisoned d_out)
__global__ __launch_bounds__(256) void gemm_kernel(
    const float* __restrict__ x,
    const float* __restrict__ w,      // [128,64] row-major
    const float* __restrict__ bias,   // [64]
    float* __restrict__ out,          // [N,64]
    int n)
{
    __shared__ float  xs[32 * 128];   // 16 KB
    __shared__ float4 ws[128 * 16];   // 32 KB

    const int tid = threadIdx.x;
    const int r0  = blockIdx.x * 32;

    const float4* w4 = (const float4*)w;
    #pragma unroll
    for (int i = tid; i < 2048; i += 256) ws[i] = w4[i];

    const float4* x4  = (const float4*)x;
    float4*       xs4 = (float4*)xs;
    #pragma unroll
    for (int i = tid; i < 1024; i += 256) {
        int row = i >> 5, c4 = i & 31;
        int r = r0 + row;
        xs4[i] = (r < n) ? x4[(size_t)r * 32 + c4] : make_float4(0.f, 0.f, 0.f, 0.f);
    }
    __syncthreads();

    const int tx = tid & 15;
    const int ty = tid >> 4;

    float4 acc0 = make_float4(0.f, 0.f, 0.f, 0.f);
    float4 acc1 = make_float4(0.f, 0.f, 0.f, 0.f);
    const float* xrow0 = &xs[(ty * 2 + 0) * 128];
    const float* xrow1 = &xs[(ty * 2 + 1) * 128];

    #pragma unroll 8
    for (int k = 0; k < 128; k++) {
        float4 wv = ws[k * 16 + tx];
        float a0 = xrow0[k];
        float a1 = xrow1[k];
        acc0.x += a0 * wv.x; acc0.y += a0 * wv.y; acc0.z += a0 * wv.z; acc0.w += a0 * wv.w;
        acc1.x += a1 * wv.x; acc1.y += a1 * wv.y; acc1.z += a1 * wv.z; acc1.w += a1 * wv.w;
    }

    float4 bv   = ((const float4*)bias)[tx];
    float4* xw4 = (float4*)g_xw;
    float4* out4 = (float4*)out;

    #pragma unroll
    for (int i = 0; i < 2; i++) {
        int r = r0 + ty * 2 + i;
        if (r < n) {
            float4 a = i ? acc1 : acc0;
            xw4[(size_t)r * 16 + tx] = a;
            float di = g_dinv[r];
            float dd = di * di;
            float4 o;
            o.x = a.x * dd + bv.x;
            o.y = a.y * dd + bv.y;
            o.z = a.z * dd + bv.z;
            o.w = a.w * dd + bv.w;
            out4[(size_t)r * 16 + tx] = o;
        }
    }
}

// ---------------------------------------------------------------------------
// Gather-reduce: one warp per node. Lane owns cols [2*lane, 2*lane+1].
__global__ __launch_bounds__(256) void gather_kernel(
    float* __restrict__ out, int n)
{
    int wid  = (blockIdx.x * blockDim.x + threadIdx.x) >> 5;
    int lane = threadIdx.x & 31;
    if (wid >= n) return;

    int start = g_rowptr[wid];
    int end   = g_rowptr[wid + 1];
    float di  = g_dinv[wid];

    float2 acc = make_float2(0.f, 0.f);

    #pragma unroll 4
    for (int k = start; k < end; k++) {
        int s = __ldg(&g_esrc[k]);                 // broadcast across warp
        float nrm = di * __ldg(&g_dinv[s]);
        float2 v = *(const float2*)(g_xw + (size_t)s * 64 + lane * 2);
        acc.x += v.x * nrm;
        acc.y += v.y * nrm;
    }

    float2* o = (float2*)(out + (size_t)wid * 64);
    float2 cur = o[lane];
    cur.x += acc.x;
    cur.y += acc.y;
    o[lane] = cur;
}

// ---------------------------------------------------------------------------
extern "C" void kernel_launch(void* const* d_in, const int* in_sizes, int n_in,
                              void* d_out, int out_size) {
    const float* x    = (const float*)d_in[0];
    const int*   ei   = (const int*)d_in[1];     // [2, E] int32
    const float* w    = (const float*)d_in[2];   // [128, 64]
    const float* bias = (const float*)d_in[3];   // [64]
    float*       out  = (float*)d_out;

    const int n = in_sizes[0] / IN_C;
    const int e = in_sizes[1] / 2;

    const int* src = ei;        // edge_index[0]
    const int* dst = ei + e;    // edge_index[1]

    // CSR build (by dst) + normalization
    cnt_zero_kernel<<<(n + 255) / 256, 256>>>(n);
    hist_kernel<<<(e + 255) / 256, 256>>>(dst, e);
    dinv_kernel<<<(n + 255) / 256, 256>>>(n);

    int nsb = (n + SCAN_BLK - 1) / SCAN_BLK;     // 98
    scanA_kernel<<<nsb, SCAN_BLK>>>(n);
    scanB_kernel<<<1, 128>>>(nsb);
    scanC_kernel<<<(n + 255) / 256, 256>>>(n, e);

    fill_kernel<<<(e + 255) / 256, 256>>>(src, dst, e);

    // xw = x @ W, self-loop + bias epilogue initializes out
    gemm_kernel<<<(n + 31) / 32, 256>>>(x, w, bias, out, n);

    // atomic-free scatter: warp-per-node gather-reduce
    int blocks = (n * 32 + 255) / 256;
    gather_kernel<<<blocks, 256>>>(out, n);
}

// round 5
// speedup vs baseline: 2.2500x; 1.2477x over previous
#include <cuda_runtime.h>
#include <cuda_bf16.h>

#define MAXN 100000
#define MAXE 1600000
#define IN_C 128
#define OUT_C 64
#define SCAN_BLK 1024
#define MAX_SCAN_BLOCKS 128   // ceil(100000/1024) = 98

// ---------------------------------------------------------------------------
// Scratch (__device__ globals per allocation-free rule)
__device__ float g_xw[(size_t)MAXN * OUT_C];   // PRE-SCALED features xw*dinv [N,64]
__device__ int   g_cnt[MAXN];                  // histogram -> running fill offsets
__device__ int   g_rowptr[MAXN + 1];           // CSR row pointers (by dst)
__device__ int   g_esrc[MAXE];                 // src ids sorted by dst
__device__ float g_dinv[MAXN];                 // rsqrt(deg)
__device__ int   g_blocksum[MAX_SCAN_BLOCKS];
__device__ int   g_blockoff[MAX_SCAN_BLOCKS];

// ---------------------------------------------------------------------------
// f32x2 packed helpers (sm_103a)
__device__ __forceinline__ unsigned long long pack2(float lo, float hi) {
    unsigned long long r;
    asm("mov.b64 %0, {%1, %2};" : "=l"(r) : "f"(lo), "f"(hi));
    return r;
}
__device__ __forceinline__ void unpack2(float& lo, float& hi, unsigned long long v) {
    asm("mov.b64 {%0, %1}, %2;" : "=f"(lo), "=f"(hi) : "l"(v));
}
__device__ __forceinline__ void fma2(unsigned long long& acc,
                                     unsigned long long a, unsigned long long b) {
    asm("fma.rn.f32x2 %0, %1, %2, %0;" : "+l"(acc) : "l"(a), "l"(b));
}

// ---------------------------------------------------------------------------
__global__ void cnt_zero_kernel(int n) {
    int i = blockIdx.x * blockDim.x + threadIdx.x;
    if (i < n) g_cnt[i] = 0;
}

__global__ void hist_kernel(const int* __restrict__ dst, int e) {
    int i = blockIdx.x * blockDim.x + threadIdx.x;
    if (i < e) atomicAdd(&g_cnt[dst[i]], 1);
}

// Scan pass A: per-block exclusive scan of g_cnt; also computes dinv (fused).
__global__ __launch_bounds__(SCAN_BLK) void scanA_kernel(int n) {
    __shared__ int sh[SCAN_BLK];
    int i = blockIdx.x * SCAN_BLK + threadIdx.x;
    int v = (i < n) ? g_cnt[i] : 0;
    if (i < n) g_dinv[i] = rsqrtf((float)(v + 1));   // +1 self-loop
    sh[threadIdx.x] = v;
    __syncthreads();
    #pragma unroll
    for (int off = 1; off < SCAN_BLK; off <<= 1) {
        int t = (threadIdx.x >= off) ? sh[threadIdx.x - off] : 0;
        __syncthreads();
        sh[threadIdx.x] += t;
        __syncthreads();
    }
    if (i < n) g_rowptr[i] = sh[threadIdx.x] - v;   // exclusive, block-local
    if (threadIdx.x == SCAN_BLK - 1) g_blocksum[blockIdx.x] = sh[SCAN_BLK - 1];
}

// Pass B: exclusive scan of block sums.
__global__ __launch_bounds__(128) void scanB_kernel(int nblocks) {
    __shared__ int sh[128];
    int v = (threadIdx.x < nblocks) ? g_blocksum[threadIdx.x] : 0;
    sh[threadIdx.x] = v;
    __syncthreads();
    #pragma unroll
    for (int off = 1; off < 128; off <<= 1) {
        int t = (threadIdx.x >= off) ? sh[threadIdx.x - off] : 0;
        __syncthreads();
        sh[threadIdx.x] += t;
        __syncthreads();
    }
    if (threadIdx.x < nblocks) g_blockoff[threadIdx.x] = sh[threadIdx.x] - v;
}

// Pass C: add block offsets; init g_cnt to row starts; rowptr[n]=e.
__global__ void scanC_kernel(int n, int e) {
    int i = blockIdx.x * blockDim.x + threadIdx.x;
    if (i < n) {
        int r = g_rowptr[i] + g_blockoff[i / SCAN_BLK];
        g_rowptr[i] = r;
        g_cnt[i]    = r;
    }
    if (i == 0) g_rowptr[n] = e;
}

// Scatter edge sources into dst-sorted order.
__global__ void fill_kernel(const int* __restrict__ src,
                            const int* __restrict__ dst, int e) {
    int i = blockIdx.x * blockDim.x + threadIdx.x;
    if (i < e) {
        int d = dst[i];
        int pos = atomicAdd(&g_cnt[d], 1);
        g_esrc[pos] = src[i];
    }
}

// ---------------------------------------------------------------------------
// GEMM: g_xw[r] = (x[r] @ W) * dinv[r]   (pre-scaled; no out write here)
// Block tile 128 rows x 64 cols, 256 threads, thread = 8 rows x 4 cols.
// K in 4 chunks of 32. Inner loop uses packed fma.rn.f32x2.
#define KCH 32
#define XS_STRIDE 34   // 32 k + 2 pad floats; 8-row delta = 272 % 32 = 16 (no conflict)
__global__ __launch_bounds__(256) void gemm_kernel(
    const float* __restrict__ x,
    const float* __restrict__ w,      // [128,64] row-major
    int n)
{
    __shared__ float4 ws[KCH * 16];            // 8 KB  (W k-chunk)
    __shared__ float  xs[128 * XS_STRIDE];     // 17.4 KB (x k-chunk, padded)

    const int tid  = threadIdx.x;
    const int warp = tid >> 5;
    const int lane = tid & 31;
    const int tx   = lane & 15;                // 4 cols (float4 of W)
    const int rowbase = warp * 16 + (lane >> 4) * 8;  // 8 local rows
    const int r0   = blockIdx.x * 128;

    unsigned long long acc[8][2];
    #pragma unroll
    for (int r = 0; r < 8; r++) { acc[r][0] = 0ull; acc[r][1] = 0ull; }

    const float4* w4 = (const float4*)w;
    const float2* x2 = (const float2*)x;
    float2* xs2 = (float2*)xs;   // row stride = XS_STRIDE/2 = 17 float2

    for (int ch = 0; ch < 4; ch++) {
        __syncthreads();
        // W chunk: 32 k-rows x 16 float4 = 512 float4
        #pragma unroll
        for (int i = tid; i < KCH * 16; i += 256)
            ws[i] = w4[ch * (KCH * 16) + i];
        // x chunk: 128 rows x 16 float2
        #pragma unroll
        for (int i = tid; i < 128 * 16; i += 256) {
            int row = i >> 4, c2 = i & 15;
            int r = r0 + row;
            xs2[row * 17 + c2] = (r < n)
                ? x2[(size_t)r * 64 + ch * 16 + c2]
                : make_float2(0.f, 0.f);
        }
        __syncthreads();

        #pragma unroll
        for (int k = 0; k < KCH; k++) {
            float4 wv = ws[k * 16 + tx];
            unsigned long long w01 = pack2(wv.x, wv.y);
            unsigned long long w23 = pack2(wv.z, wv.w);
            #pragma unroll
            for (int r = 0; r < 8; r++) {
                float a = xs[(rowbase + r) * XS_STRIDE + k];
                unsigned long long aa = pack2(a, a);
                fma2(acc[r][0], aa, w01);
                fma2(acc[r][1], aa, w23);
            }
        }
    }

    // Epilogue: scale by dinv and store to g_xw
    float4* xw4 = (float4*)g_xw;
    #pragma unroll
    for (int r = 0; r < 8; r++) {
        int row = r0 + rowbase + r;
        if (row < n) {
            float di = g_dinv[row];
            float4 o;
            unpack2(o.x, o.y, acc[r][0]);
            unpack2(o.z, o.w, acc[r][1]);
            o.x *= di; o.y *= di; o.z *= di; o.w *= di;
            xw4[(size_t)row * 16 + tx] = o;
        }
    }
}

// ---------------------------------------------------------------------------
// Gather-reduce: one warp per node, write-once.
//   out[i] = (sum_edges xws[src] + xws[i]) * dinv[i] + bias
__global__ __launch_bounds__(256) void gather_kernel(
    const float* __restrict__ bias,
    float* __restrict__ out, int n)
{
    int wid  = (blockIdx.x * blockDim.x + threadIdx.x) >> 5;
    int lane = threadIdx.x & 31;
    if (wid >= n) return;

    int start = g_rowptr[wid];
    int end   = g_rowptr[wid + 1];
    float di  = g_dinv[wid];

    // self-loop term (xws already scaled by dinv[src])
    float2 acc = *(const float2*)(g_xw + (size_t)wid * 64 + lane * 2);

    #pragma unroll 4
    for (int k = start; k < end; k++) {
        int s = __ldg(&g_esrc[k]);                 // broadcast across warp
        float2 v = *(const float2*)(g_xw + (size_t)s * 64 + lane * 2);
        acc.x += v.x;
        acc.y += v.y;
    }

    float2 bv = __ldg((const float2*)bias + lane);
    float2 o;
    o.x = acc.x * di + bv.x;
    o.y = acc.y * di + bv.y;
    ((float2*)(out + (size_t)wid * 64))[lane] = o;
}

// ---------------------------------------------------------------------------
extern "C" void kernel_launch(void* const* d_in, const int* in_sizes, int n_in,
                              void* d_out, int out_size) {
    const float* x    = (const float*)d_in[0];
    const int*   ei   = (const int*)d_in[1];     // [2, E] int32
    const float* w    = (const float*)d_in[2];   // [128, 64]
    const float* bias = (const float*)d_in[3];   // [64]
    float*       out  = (float*)d_out;

    const int n = in_sizes[0] / IN_C;
    const int e = in_sizes[1] / 2;

    const int* src = ei;        // edge_index[0]
    const int* dst = ei + e;    // edge_index[1]

    // CSR build (by dst) + normalization
    cnt_zero_kernel<<<(n + 255) / 256, 256>>>(n);
    hist_kernel<<<(e + 255) / 256, 256>>>(dst, e);

    int nsb = (n + SCAN_BLK - 1) / SCAN_BLK;     // 98
    scanA_kernel<<<nsb, SCAN_BLK>>>(n);          // also computes dinv
    scanB_kernel<<<1, 128>>>(nsb);
    scanC_kernel<<<(n + 255) / 256, 256>>>(n, e);

    fill_kernel<<<(e + 255) / 256, 256>>>(src, dst, e);

    // pre-scaled projection: g_xw = (x @ W) * dinv
    gemm_kernel<<<(n + 127) / 128, 256>>>(x, w, n);

    // write-once gather (also initializes all of d_out)
    int blocks = (n * 32 + 255) / 256;
    gather_kernel<<<blocks, 256>>>(bias, out, n);
}